// round 14
// baseline (speedup 1.0000x reference)
#include <cuda_runtime.h>
#include <cuda_fp16.h>
#include <stdint.h>

// gcnlayer2: out1 = A1 @ x1 ; out2 = A2 @ x2
// R14 = R13 (fp16 gathers; spmm 68.5us now ISSUE/ALU-bound: issue 56%,
//       alu 44%, L2 only 17%) with two changes:
//   1) spmm tail-split: main loop unmasked (kills 16 ISETP/SEL per iter on
//      the issue-bound path); tail = 3 parallel masked gathers (extra traffic
//      is free at L2=17%). R11 showed this hurt when MEMORY-bound; regime
//      has flipped.
//   2) zero_cnt + fp16 convert fused into one prep kernel (-1 launch).

#define DFEAT 64
#define H2_PER_ROW (DFEAT / 2)    // 32 half2 per feature row (128B)
#define NN 65536                  // n_nodes
#define CAP 64                    // slots per row (deg ~ Poisson(16))

// Device-global scratch.
__device__ int     g_cnt[2][NN];
__device__ int2    g_slot[2][(size_t)NN * CAP];      // (col, val_bits)
__device__ __half2 g_xh[2][(size_t)NN * H2_PER_ROW]; // fp16 copies of x1, x2

// -------------------------------------------------------------- kernels ----

// Fused prep: zero counters (first 32K threads) + fp32->fp16 convert (2M thr).
__global__ void __launch_bounds__(256) prep_kernel(
    const float4* __restrict__ x1,
    const float4* __restrict__ x2,
    int ncnt4,    // NN*2/4 int4 counter words
    int n4)       // NN*DFEAT/4 float4 per matrix
{
    int i = blockIdx.x * blockDim.x + threadIdx.x;
    if (i < ncnt4) {
        ((int4*)g_cnt)[i] = make_int4(0, 0, 0, 0);
    }
    int j = i - ncnt4;
    if (j >= 0 && j < 2 * n4) {
        int m = j < n4 ? 0 : 1;
        int k = m ? j - n4 : j;
        float4 v = __ldg(m ? &x2[k] : &x1[k]);
        __half2* dst = &g_xh[m][(size_t)k * 2];
        dst[0] = __floats2half2_rn(v.x, v.y);
        dst[1] = __floats2half2_rn(v.z, v.w);
    }
}

// Bucket edges by row: 4 edges per thread, vectorized metadata loads,
// 4 independent ATOMGs in flight. (Confirmed: ~16us.)
__global__ void __launch_bounds__(256) bucket_kernel(
    const int4*   __restrict__ r1, const int4* __restrict__ c1,
    const float4* __restrict__ v1,
    const int4*   __restrict__ r2, const int4* __restrict__ c2,
    const float4* __restrict__ v2,
    int n_groups)    // n_edges / 4 per matrix
{
    int t = blockIdx.x * blockDim.x + threadIdx.x;
    if (t >= 2 * n_groups) return;
    int m = t < n_groups ? 0 : 1;
    int g = m ? t - n_groups : t;

    int4   r = __ldg(m ? &r2[g] : &r1[g]);
    int4   c = __ldg(m ? &c2[g] : &c1[g]);
    float4 v = __ldg(m ? &v2[g] : &v1[g]);

    int p0 = atomicAdd(&g_cnt[m][r.x], 1);
    int p1 = atomicAdd(&g_cnt[m][r.y], 1);
    int p2 = atomicAdd(&g_cnt[m][r.z], 1);
    int p3 = atomicAdd(&g_cnt[m][r.w], 1);

    if (p0 < CAP) g_slot[m][(size_t)r.x * CAP + p0] = make_int2(c.x, __float_as_int(v.x));
    if (p1 < CAP) g_slot[m][(size_t)r.y * CAP + p1] = make_int2(c.y, __float_as_int(v.y));
    if (p2 < CAP) g_slot[m][(size_t)r.z * CAP + p2] = make_int2(c.z, __float_as_int(v.z));
    if (p3 < CAP) g_slot[m][(size_t)r.w * CAP + p3] = make_int2(c.w, __float_as_int(v.w));
}

// Warp-per-row gather SpMM — fp16 gathers, fp32 accumulate.
// Main loop UNMASKED (issue-bound regime); tail = 3 parallel masked gathers.
__global__ void __launch_bounds__(256) spmm_kernel(
    float* __restrict__ out1,
    float* __restrict__ out2,
    int n_nodes)
{
    int warp = (blockIdx.x * blockDim.x + threadIdx.x) >> 5;
    int lane = threadIdx.x & 31;
    if (warp >= 2 * n_nodes) return;

    int m = warp < n_nodes ? 0 : 1;
    int r = m ? warp - n_nodes : warp;
    const __half2* x = g_xh[m];
    float* out      = m ? out2 : out1;

    int n = g_cnt[m][r];
    if (n > CAP) n = CAP;

    const int4* ep = (const int4*)&g_slot[m][(size_t)r * CAP];  // 2 edges / int4

    float2 acc = make_float2(0.f, 0.f);
    int iters = n >> 2;           // full 4-edge batches, unmasked
    int tail  = n & 3;

    if (iters > 0) {
        int4 e01 = __ldg(ep + 0);
        int4 e23 = __ldg(ep + 1);
        for (int it = 0; it < iters; it++) {
            int4 n01, n23;
            if (it + 1 < iters) {           // prefetch next batch
                n01 = __ldg(ep + 2 * it + 2);
                n23 = __ldg(ep + 2 * it + 3);
            }
            float v0 = __int_as_float(e01.y);
            float v1 = __int_as_float(e01.w);
            float v2 = __int_as_float(e23.y);
            float v3 = __int_as_float(e23.w);

            // 4 independent coalesced 128B gathers in flight.
            __half2 ha = __ldg(&x[(size_t)e01.x * H2_PER_ROW + lane]);
            __half2 hb = __ldg(&x[(size_t)e01.z * H2_PER_ROW + lane]);
            __half2 hc = __ldg(&x[(size_t)e23.x * H2_PER_ROW + lane]);
            __half2 hd = __ldg(&x[(size_t)e23.z * H2_PER_ROW + lane]);

            float2 xa = __half22float2(ha);
            float2 xb = __half22float2(hb);
            float2 xc = __half22float2(hc);
            float2 xd = __half22float2(hd);

            acc.x += v0 * xa.x + v1 * xb.x + v2 * xc.x + v3 * xd.x;
            acc.y += v0 * xa.y + v1 * xb.y + v2 * xc.y + v3 * xd.y;

            e01 = n01;
            e23 = n23;
        }
    }

    // Tail: up to 3 edges, gathers issued in parallel, values masked to 0.
    if (tail) {
        const int2* es = (const int2*)ep + (n & ~3);
        int2 t0 = __ldg(es + 0);
        int2 t1 = (tail > 1) ? __ldg(es + 1) : make_int2(0, 0);
        int2 t2 = (tail > 2) ? __ldg(es + 2) : make_int2(0, 0);
        __half2 ha = __ldg(&x[(size_t)t0.x * H2_PER_ROW + lane]);
        __half2 hb = __ldg(&x[(size_t)t1.x * H2_PER_ROW + lane]);
        __half2 hc = __ldg(&x[(size_t)t2.x * H2_PER_ROW + lane]);
        float2 xa = __half22float2(ha);
        float2 xb = __half22float2(hb);
        float2 xc = __half22float2(hc);
        float v0 = __int_as_float(t0.y);
        float v1 = __int_as_float(t1.y);
        float v2 = __int_as_float(t2.y);
        acc.x += v0 * xa.x + v1 * xb.x + v2 * xc.x;
        acc.y += v0 * xa.y + v1 * xb.y + v2 * xc.y;
    }

    // Single vector store; every row written -> no output zeroing needed.
    ((float2*)(out + (size_t)r * DFEAT))[lane] = acc;
}

// --------------------------------------------------------------- launch ----

extern "C" void kernel_launch(void* const* d_in, const int* in_sizes, int n_in,
                              void* d_out, int out_size) {
    const float* x1      = (const float*)d_in[0];
    const float* x2      = (const float*)d_in[1];
    const int*   a1_rows = (const int*)d_in[2];
    const int*   a1_cols = (const int*)d_in[3];
    const float* a1_vals = (const float*)d_in[4];
    const int*   a2_rows = (const int*)d_in[5];
    const int*   a2_cols = (const int*)d_in[6];
    const float* a2_vals = (const float*)d_in[7];

    float* out  = (float*)d_out;
    int n_edges = in_sizes[2];               // 1048576
    int n_nodes = in_sizes[0] / DFEAT;       // 65536
    int half    = n_nodes * DFEAT;
    int n_groups = n_edges / 4;

    // 1) fused prep: zero counters + fp16 convert
    {
        int ncnt4 = 2 * n_nodes / 4;         // 32768
        int n4 = n_nodes * DFEAT / 4;        // 1M float4 per matrix
        int total = ncnt4 + 2 * n4;
        prep_kernel<<<(total + 255) / 256, 256>>>(
            (const float4*)x1, (const float4*)x2, ncnt4, n4);
    }

    // 2) bucket edges by row (both matrices, one pass)
    {
        int total = 2 * n_groups;
        bucket_kernel<<<(total + 255) / 256, 256>>>(
            (const int4*)a1_rows, (const int4*)a1_cols, (const float4*)a1_vals,
            (const int4*)a2_rows, (const int4*)a2_cols, (const float4*)a2_vals,
            n_groups);
    }

    // 3) warp-per-row gather SpMM (fp16 gathers, fp32 accumulate)
    {
        long long total_threads = 2LL * n_nodes * 32;
        int threads = 256;
        long long blocks = (total_threads + threads - 1) / threads;
        spmm_kernel<<<(unsigned)blocks, threads>>>(out, out + half, n_nodes);
    }
}

// round 15
// speedup vs baseline: 1.1800x; 1.1800x over previous
#include <cuda_runtime.h>
#include <cuda_fp16.h>
#include <stdint.h>

// gcnlayer2: out1 = A1 @ x1 ; out2 = A2 @ x2
// R15 = R13 (fp16 gathers, masked 4-edge pipelined spmm loop — tail-split is
//       confirmed-bad twice: serial tail chain) + fused prep + vectorized
//       bucket, with ONE spmm change:
//       2 rows per warp / 16-lane groups / uint2 (8B) gathers. In fp16 a row
//       is 128B, so 32x4B lanes wasted issue slots; now one LDG serves 256B
//       across 2 rows -> gather instructions per row halve (issue-bound
//       kernel: issue 56%, L2 17% in R13).

#define DFEAT 64
#define H2_PER_ROW (DFEAT / 2)    // 32 half2 per feature row (128B)
#define U2_PER_ROW (DFEAT / 4)    // 16 uint2  per feature row
#define NN 65536                  // n_nodes
#define CAP 64                    // slots per row (deg ~ Poisson(16))

// Device-global scratch.
__device__ int     g_cnt[2][NN];
__device__ int2    g_slot[2][(size_t)NN * CAP];      // (col, val_bits)
__device__ __half2 g_xh[2][(size_t)NN * H2_PER_ROW]; // fp16 copies of x1, x2

// -------------------------------------------------------------- kernels ----

// Fused prep: zero counters + fp32->fp16 convert.
__global__ void __launch_bounds__(256) prep_kernel(
    const float4* __restrict__ x1,
    const float4* __restrict__ x2,
    int ncnt4,    // NN*2/4 int4 counter words
    int n4)       // NN*DFEAT/4 float4 per matrix
{
    int i = blockIdx.x * blockDim.x + threadIdx.x;
    if (i < ncnt4) {
        ((int4*)g_cnt)[i] = make_int4(0, 0, 0, 0);
    }
    int j = i - ncnt4;
    if (j >= 0 && j < 2 * n4) {
        int m = j < n4 ? 0 : 1;
        int k = m ? j - n4 : j;
        float4 v = __ldg(m ? &x2[k] : &x1[k]);
        __half2* dst = &g_xh[m][(size_t)k * 2];
        dst[0] = __floats2half2_rn(v.x, v.y);
        dst[1] = __floats2half2_rn(v.z, v.w);
    }
}

// Bucket edges by row: 4 edges per thread, vectorized metadata loads,
// 4 independent ATOMGs in flight. (Confirmed: ~16us.)
__global__ void __launch_bounds__(256) bucket_kernel(
    const int4*   __restrict__ r1, const int4* __restrict__ c1,
    const float4* __restrict__ v1,
    const int4*   __restrict__ r2, const int4* __restrict__ c2,
    const float4* __restrict__ v2,
    int n_groups)    // n_edges / 4 per matrix
{
    int t = blockIdx.x * blockDim.x + threadIdx.x;
    if (t >= 2 * n_groups) return;
    int m = t < n_groups ? 0 : 1;
    int g = m ? t - n_groups : t;

    int4   r = __ldg(m ? &r2[g] : &r1[g]);
    int4   c = __ldg(m ? &c2[g] : &c1[g]);
    float4 v = __ldg(m ? &v2[g] : &v1[g]);

    int p0 = atomicAdd(&g_cnt[m][r.x], 1);
    int p1 = atomicAdd(&g_cnt[m][r.y], 1);
    int p2 = atomicAdd(&g_cnt[m][r.z], 1);
    int p3 = atomicAdd(&g_cnt[m][r.w], 1);

    if (p0 < CAP) g_slot[m][(size_t)r.x * CAP + p0] = make_int2(c.x, __float_as_int(v.x));
    if (p1 < CAP) g_slot[m][(size_t)r.y * CAP + p1] = make_int2(c.y, __float_as_int(v.y));
    if (p2 < CAP) g_slot[m][(size_t)r.z * CAP + p2] = make_int2(c.z, __float_as_int(v.z));
    if (p3 < CAP) g_slot[m][(size_t)r.w * CAP + p3] = make_int2(c.w, __float_as_int(v.w));
}

// Warp-per-2-rows gather SpMM — fp16 gathers (uint2 = 8B per lane), fp32 acc.
// 16-lane group per row; masked 4-edge pipelined loop (R13 form).
__global__ void __launch_bounds__(256) spmm_kernel(
    float* __restrict__ out1,
    float* __restrict__ out2,
    int n_nodes)
{
    int tid  = blockIdx.x * blockDim.x + threadIdx.x;
    int warp = tid >> 5;
    int lane = threadIdx.x & 31;
    int half_id = lane >> 4;      // which of the warp's 2 rows
    int gl      = lane & 15;      // lane within the 16-lane group

    int g = warp * 2 + half_id;   // row slot across both matrices
    if (g >= 2 * n_nodes) return;

    int m = g < n_nodes ? 0 : 1;
    int r = m ? g - n_nodes : g;
    const uint2* x = (const uint2*)g_xh[m];
    float* out     = m ? out2 : out1;

    int n = g_cnt[m][r];
    if (n > CAP) n = CAP;

    const int4* ep = (const int4*)&g_slot[m][(size_t)r * CAP];  // 2 edges / int4

    float4 acc = make_float4(0.f, 0.f, 0.f, 0.f);
    int iters = (n + 3) >> 2;     // 4 edges / iteration, masked (R13 form)

    if (iters > 0) {
        int4 e01 = __ldg(ep + 0);
        int4 e23 = __ldg(ep + 1);
        for (int it = 0; it < iters; it++) {
            int4 n01, n23;
            if (it + 1 < iters) {
                n01 = __ldg(ep + 2 * it + 2);
                n23 = __ldg(ep + 2 * it + 3);
            }
            int k = it * 4;
            int   c0 = (k + 0 < n) ? e01.x : 0;
            float v0 = (k + 0 < n) ? __int_as_float(e01.y) : 0.f;
            int   c1 = (k + 1 < n) ? e01.z : 0;
            float v1 = (k + 1 < n) ? __int_as_float(e01.w) : 0.f;
            int   c2 = (k + 2 < n) ? e23.x : 0;
            float v2 = (k + 2 < n) ? __int_as_float(e23.y) : 0.f;
            int   c3 = (k + 3 < n) ? e23.z : 0;
            float v3 = (k + 3 < n) ? __int_as_float(e23.w) : 0.f;

            // 4 independent gathers; warp covers 2 rows x 128B per LDG batch.
            uint2 ua = __ldg(&x[(size_t)c0 * U2_PER_ROW + gl]);
            uint2 ub = __ldg(&x[(size_t)c1 * U2_PER_ROW + gl]);
            uint2 uc = __ldg(&x[(size_t)c2 * U2_PER_ROW + gl]);
            uint2 ud = __ldg(&x[(size_t)c3 * U2_PER_ROW + gl]);

            float2 a0 = __half22float2(*(__half2*)&ua.x);
            float2 a1 = __half22float2(*(__half2*)&ua.y);
            float2 b0 = __half22float2(*(__half2*)&ub.x);
            float2 b1 = __half22float2(*(__half2*)&ub.y);
            float2 c0f = __half22float2(*(__half2*)&uc.x);
            float2 c1f = __half22float2(*(__half2*)&uc.y);
            float2 d0 = __half22float2(*(__half2*)&ud.x);
            float2 d1 = __half22float2(*(__half2*)&ud.y);

            acc.x += v0 * a0.x + v1 * b0.x + v2 * c0f.x + v3 * d0.x;
            acc.y += v0 * a0.y + v1 * b0.y + v2 * c0f.y + v3 * d0.y;
            acc.z += v0 * a1.x + v1 * b1.x + v2 * c1f.x + v3 * d1.x;
            acc.w += v0 * a1.y + v1 * b1.y + v2 * c1f.y + v3 * d1.y;

            e01 = n01;
            e23 = n23;
        }
    }

    // 16 lanes x float4 = 256B coalesced store per row.
    ((float4*)(out + (size_t)r * DFEAT))[gl] = acc;
}

// --------------------------------------------------------------- launch ----

extern "C" void kernel_launch(void* const* d_in, const int* in_sizes, int n_in,
                              void* d_out, int out_size) {
    const float* x1      = (const float*)d_in[0];
    const float* x2      = (const float*)d_in[1];
    const int*   a1_rows = (const int*)d_in[2];
    const int*   a1_cols = (const int*)d_in[3];
    const float* a1_vals = (const float*)d_in[4];
    const int*   a2_rows = (const int*)d_in[5];
    const int*   a2_cols = (const int*)d_in[6];
    const float* a2_vals = (const float*)d_in[7];

    float* out  = (float*)d_out;
    int n_edges = in_sizes[2];               // 1048576
    int n_nodes = in_sizes[0] / DFEAT;       // 65536
    int half    = n_nodes * DFEAT;
    int n_groups = n_edges / 4;

    // 1) fused prep: zero counters + fp16 convert
    {
        int ncnt4 = 2 * n_nodes / 4;         // 32768
        int n4 = n_nodes * DFEAT / 4;        // 1M float4 per matrix
        int total = ncnt4 + 2 * n4;
        prep_kernel<<<(total + 255) / 256, 256>>>(
            (const float4*)x1, (const float4*)x2, ncnt4, n4);
    }

    // 2) bucket edges by row (both matrices, one pass)
    {
        int total = 2 * n_groups;
        bucket_kernel<<<(total + 255) / 256, 256>>>(
            (const int4*)a1_rows, (const int4*)a1_cols, (const float4*)a1_vals,
            (const int4*)a2_rows, (const int4*)a2_cols, (const float4*)a2_vals,
            n_groups);
    }

    // 3) warp-per-2-rows gather SpMM (fp16 gathers, fp32 accumulate)
    {
        long long total_threads = 1LL * n_nodes * 32;   // 1 warp per 2 rows
        int threads = 256;
        long long blocks = (total_threads + threads - 1) / threads;
        spmm_kernel<<<(unsigned)blocks, threads>>>(out, out + half, n_nodes);
    }
}

// round 16
// speedup vs baseline: 1.1816x; 1.0014x over previous
#include <cuda_runtime.h>
#include <cuda_fp16.h>
#include <stdint.h>

// gcnlayer2: out1 = A1 @ x1 ; out2 = A2 @ x2
// R16 = R15 (WIN, 92.6us: fp16 gathers, 2-rows-per-warp masked pipelined spmm)
//       with the prep region restructured; spmm kernel is BYTE-IDENTICAL:
//   1) convert + bucket fused into ONE kernel (disjoint thread ranges,
//      bucket range first). Convert is DRAM-bound, bucket is atomic-latency
//      bound -> they overlap instead of serializing (26us -> ~13us).
//   2) bucket at 8 edges/thread: MLP=8 on the 318cyc ATOMG path.
//   3) counter zeroing back to its own tiny kernel (must precede bucket
//      atomics; in-spmm reset remains banned per R9).

#define DFEAT 64
#define H2_PER_ROW (DFEAT / 2)    // 32 half2 per feature row (128B)
#define U2_PER_ROW (DFEAT / 4)    // 16 uint2  per feature row
#define NN 65536                  // n_nodes
#define CAP 64                    // slots per row (deg ~ Poisson(16))

// Device-global scratch.
__device__ int     g_cnt[2][NN];
__device__ int2    g_slot[2][(size_t)NN * CAP];      // (col, val_bits)
__device__ __half2 g_xh[2][(size_t)NN * H2_PER_ROW]; // fp16 copies of x1, x2

// -------------------------------------------------------------- kernels ----

__global__ void zero_cnt_kernel(int n4) {
    int i = blockIdx.x * blockDim.x + threadIdx.x;
    if (i < n4) ((int4*)g_cnt)[i] = make_int4(0, 0, 0, 0);
}

// Fused convert + bucket. Thread ranges:
//   [0, nbucket)            : bucket, 8 edges/thread (scheduled first)
//   [nbucket, nbucket+2*n4) : fp32 -> fp16 convert, one float4/thread
__global__ void __launch_bounds__(256) fused_prep_kernel(
    const int4*   __restrict__ r1, const int4* __restrict__ c1,
    const float4* __restrict__ v1,
    const int4*   __restrict__ r2, const int4* __restrict__ c2,
    const float4* __restrict__ v2,
    const float4* __restrict__ x1,
    const float4* __restrict__ x2,
    int nbucket,   // 2*n_edges/8
    int n4)        // NN*DFEAT/4 float4 per matrix
{
    int i = blockIdx.x * blockDim.x + threadIdx.x;

    if (i < nbucket) {
        // ---- bucket: 8 edges per thread, MLP=8 atomics ----
        int hb = nbucket >> 1;
        int m = i < hb ? 0 : 1;
        int g = m ? i - hb : i;            // 8-edge group index
        const int4*   rr = m ? r2 : r1;
        const int4*   cc = m ? c2 : c1;
        const float4* vv = m ? v2 : v1;

        int4   ra = __ldg(rr + 2 * g),     rb = __ldg(rr + 2 * g + 1);
        int4   ca = __ldg(cc + 2 * g),     cb = __ldg(cc + 2 * g + 1);
        float4 va = __ldg(vv + 2 * g),     vb = __ldg(vv + 2 * g + 1);

        int p0 = atomicAdd(&g_cnt[m][ra.x], 1);
        int p1 = atomicAdd(&g_cnt[m][ra.y], 1);
        int p2 = atomicAdd(&g_cnt[m][ra.z], 1);
        int p3 = atomicAdd(&g_cnt[m][ra.w], 1);
        int p4 = atomicAdd(&g_cnt[m][rb.x], 1);
        int p5 = atomicAdd(&g_cnt[m][rb.y], 1);
        int p6 = atomicAdd(&g_cnt[m][rb.z], 1);
        int p7 = atomicAdd(&g_cnt[m][rb.w], 1);

        if (p0 < CAP) g_slot[m][(size_t)ra.x * CAP + p0] = make_int2(ca.x, __float_as_int(va.x));
        if (p1 < CAP) g_slot[m][(size_t)ra.y * CAP + p1] = make_int2(ca.y, __float_as_int(va.y));
        if (p2 < CAP) g_slot[m][(size_t)ra.z * CAP + p2] = make_int2(ca.z, __float_as_int(va.z));
        if (p3 < CAP) g_slot[m][(size_t)ra.w * CAP + p3] = make_int2(ca.w, __float_as_int(va.w));
        if (p4 < CAP) g_slot[m][(size_t)rb.x * CAP + p4] = make_int2(cb.x, __float_as_int(vb.x));
        if (p5 < CAP) g_slot[m][(size_t)rb.y * CAP + p5] = make_int2(cb.y, __float_as_int(vb.y));
        if (p6 < CAP) g_slot[m][(size_t)rb.z * CAP + p6] = make_int2(cb.z, __float_as_int(vb.z));
        if (p7 < CAP) g_slot[m][(size_t)rb.w * CAP + p7] = make_int2(cb.w, __float_as_int(vb.w));
    } else {
        // ---- convert: one float4 -> two half2 ----
        int j = i - nbucket;
        if (j < 2 * n4) {
            int m = j < n4 ? 0 : 1;
            int k = m ? j - n4 : j;
            float4 v = __ldg(m ? &x2[k] : &x1[k]);
            __half2* dst = &g_xh[m][(size_t)k * 2];
            dst[0] = __floats2half2_rn(v.x, v.y);
            dst[1] = __floats2half2_rn(v.z, v.w);
        }
    }
}

// Warp-per-2-rows gather SpMM — BYTE-IDENTICAL to R15 (proven).
__global__ void __launch_bounds__(256) spmm_kernel(
    float* __restrict__ out1,
    float* __restrict__ out2,
    int n_nodes)
{
    int tid  = blockIdx.x * blockDim.x + threadIdx.x;
    int warp = tid >> 5;
    int lane = threadIdx.x & 31;
    int half_id = lane >> 4;      // which of the warp's 2 rows
    int gl      = lane & 15;      // lane within the 16-lane group

    int g = warp * 2 + half_id;   // row slot across both matrices
    if (g >= 2 * n_nodes) return;

    int m = g < n_nodes ? 0 : 1;
    int r = m ? g - n_nodes : g;
    const uint2* x = (const uint2*)g_xh[m];
    float* out     = m ? out2 : out1;

    int n = g_cnt[m][r];
    if (n > CAP) n = CAP;

    const int4* ep = (const int4*)&g_slot[m][(size_t)r * CAP];  // 2 edges / int4

    float4 acc = make_float4(0.f, 0.f, 0.f, 0.f);
    int iters = (n + 3) >> 2;     // 4 edges / iteration, masked

    if (iters > 0) {
        int4 e01 = __ldg(ep + 0);
        int4 e23 = __ldg(ep + 1);
        for (int it = 0; it < iters; it++) {
            int4 n01, n23;
            if (it + 1 < iters) {
                n01 = __ldg(ep + 2 * it + 2);
                n23 = __ldg(ep + 2 * it + 3);
            }
            int k = it * 4;
            int   c0 = (k + 0 < n) ? e01.x : 0;
            float v0 = (k + 0 < n) ? __int_as_float(e01.y) : 0.f;
            int   c1 = (k + 1 < n) ? e01.z : 0;
            float v1 = (k + 1 < n) ? __int_as_float(e01.w) : 0.f;
            int   c2 = (k + 2 < n) ? e23.x : 0;
            float v2 = (k + 2 < n) ? __int_as_float(e23.y) : 0.f;
            int   c3 = (k + 3 < n) ? e23.z : 0;
            float v3 = (k + 3 < n) ? __int_as_float(e23.w) : 0.f;

            uint2 ua = __ldg(&x[(size_t)c0 * U2_PER_ROW + gl]);
            uint2 ub = __ldg(&x[(size_t)c1 * U2_PER_ROW + gl]);
            uint2 uc = __ldg(&x[(size_t)c2 * U2_PER_ROW + gl]);
            uint2 ud = __ldg(&x[(size_t)c3 * U2_PER_ROW + gl]);

            float2 a0 = __half22float2(*(__half2*)&ua.x);
            float2 a1 = __half22float2(*(__half2*)&ua.y);
            float2 b0 = __half22float2(*(__half2*)&ub.x);
            float2 b1 = __half22float2(*(__half2*)&ub.y);
            float2 c0f = __half22float2(*(__half2*)&uc.x);
            float2 c1f = __half22float2(*(__half2*)&uc.y);
            float2 d0 = __half22float2(*(__half2*)&ud.x);
            float2 d1 = __half22float2(*(__half2*)&ud.y);

            acc.x += v0 * a0.x + v1 * b0.x + v2 * c0f.x + v3 * d0.x;
            acc.y += v0 * a0.y + v1 * b0.y + v2 * c0f.y + v3 * d0.y;
            acc.z += v0 * a1.x + v1 * b1.x + v2 * c1f.x + v3 * d1.x;
            acc.w += v0 * a1.y + v1 * b1.y + v2 * c1f.y + v3 * d1.y;

            e01 = n01;
            e23 = n23;
        }
    }

    // 16 lanes x float4 = 256B coalesced store per row.
    ((float4*)(out + (size_t)r * DFEAT))[gl] = acc;
}

// --------------------------------------------------------------- launch ----

extern "C" void kernel_launch(void* const* d_in, const int* in_sizes, int n_in,
                              void* d_out, int out_size) {
    const float* x1      = (const float*)d_in[0];
    const float* x2      = (const float*)d_in[1];
    const int*   a1_rows = (const int*)d_in[2];
    const int*   a1_cols = (const int*)d_in[3];
    const float* a1_vals = (const float*)d_in[4];
    const int*   a2_rows = (const int*)d_in[5];
    const int*   a2_cols = (const int*)d_in[6];
    const float* a2_vals = (const float*)d_in[7];

    float* out  = (float*)d_out;
    int n_edges = in_sizes[2];               // 1048576
    int n_nodes = in_sizes[0] / DFEAT;       // 65536
    int half    = n_nodes * DFEAT;

    // 1) zero per-row counters (must precede bucket atomics)
    {
        int ncnt4 = 2 * n_nodes / 4;         // 32768 int4 words
        zero_cnt_kernel<<<(ncnt4 + 255) / 256, 256>>>(ncnt4);
    }

    // 2) fused bucket (8 edges/thread, range first) + fp16 convert
    {
        int nbucket = 2 * n_edges / 8;       // 262144
        int n4 = n_nodes * DFEAT / 4;        // 1M float4 per matrix
        int total = nbucket + 2 * n4;
        fused_prep_kernel<<<(total + 255) / 256, 256>>>(
            (const int4*)a1_rows, (const int4*)a1_cols, (const float4*)a1_vals,
            (const int4*)a2_rows, (const int4*)a2_cols, (const float4*)a2_vals,
            (const float4*)x1, (const float4*)x2,
            nbucket, n4);
    }

    // 3) warp-per-2-rows gather SpMM (fp16 gathers, fp32 accumulate)
    {
        long long total_threads = 1LL * n_nodes * 32;   // 1 warp per 2 rows
        int threads = 256;
        long long blocks = (total_threads + threads - 1) / threads;
        spmm_kernel<<<(unsigned)blocks, threads>>>(out, out + half, n_nodes);
    }
}

// round 17
// speedup vs baseline: 1.3370x; 1.1315x over previous
#include <cuda_runtime.h>
#include <cuda_fp16.h>
#include <stdint.h>

// gcnlayer2: out1 = A1 @ x1 ; out2 = A2 @ x2
// R17 = R15/R16 spmm (2 rows/warp, uint2 fp16 gathers, pipelined 4-edge loop)
//       with two changes:
//   1) spmm UNMASKED via zero-slot invariant: g_slot is zero at module load
//      and slots >= n_r are never written by any launch -> tail edges read
//      (col=0, val=0.0) and contribute exactly 0. Removes ~16 ISETP/SEL per
//      iteration with NO loop-shape change (tail-split remains banned).
//   2) prep interleaved by block stripe (bid%9==0 -> bucket, else convert;
//      exact 1:8 block ratio) so atomic-latency and DRAM-stream work are
//      co-resident on every SM — fixes R16's sequential-wave fusion failure.

#define DFEAT 64
#define H2_PER_ROW (DFEAT / 2)    // 32 half2 per feature row (128B)
#define U2_PER_ROW (DFEAT / 4)    // 16 uint2  per feature row
#define NN 65536                  // n_nodes
#define CAP 64                    // slots per row (deg ~ Poisson(16))

// Device-global scratch (zero at module load; slots >= n_r stay zero forever).
__device__ int     g_cnt[2][NN];
__device__ int2    g_slot[2][(size_t)NN * CAP];      // (col, val_bits)
__device__ __half2 g_xh[2][(size_t)NN * H2_PER_ROW]; // fp16 copies of x1, x2

// -------------------------------------------------------------- kernels ----

__global__ void zero_cnt_kernel(int n4) {
    int i = blockIdx.x * blockDim.x + threadIdx.x;
    if (i < n4) ((int4*)g_cnt)[i] = make_int4(0, 0, 0, 0);
}

// Interleaved prep: blocks with bid%9==0 bucket (8 edges/thread, 1024 blocks),
// the rest convert fp32->fp16 (one float4/thread, 8192 blocks).
__global__ void __launch_bounds__(256) prep_kernel(
    const int4*   __restrict__ r1, const int4* __restrict__ c1,
    const float4* __restrict__ v1,
    const int4*   __restrict__ r2, const int4* __restrict__ c2,
    const float4* __restrict__ v2,
    const float4* __restrict__ x1,
    const float4* __restrict__ x2,
    int nbucket,   // 2*n_edges/8 bucket threads
    int n4)        // NN*DFEAT/4 float4 per matrix
{
    int bid = blockIdx.x;

    if (bid % 9 == 0) {
        // ---- bucket: 8 edges per thread ----
        int i = (bid / 9) * blockDim.x + threadIdx.x;
        if (i >= nbucket) return;
        int hb = nbucket >> 1;
        int m = i < hb ? 0 : 1;
        int g = m ? i - hb : i;            // 8-edge group index
        const int4*   rr = m ? r2 : r1;
        const int4*   cc = m ? c2 : c1;
        const float4* vv = m ? v2 : v1;

        int4   ra = __ldg(rr + 2 * g),  rb = __ldg(rr + 2 * g + 1);
        int4   ca = __ldg(cc + 2 * g),  cb = __ldg(cc + 2 * g + 1);
        float4 va = __ldg(vv + 2 * g),  vb = __ldg(vv + 2 * g + 1);

        int p0 = atomicAdd(&g_cnt[m][ra.x], 1);
        int p1 = atomicAdd(&g_cnt[m][ra.y], 1);
        int p2 = atomicAdd(&g_cnt[m][ra.z], 1);
        int p3 = atomicAdd(&g_cnt[m][ra.w], 1);
        int p4 = atomicAdd(&g_cnt[m][rb.x], 1);
        int p5 = atomicAdd(&g_cnt[m][rb.y], 1);
        int p6 = atomicAdd(&g_cnt[m][rb.z], 1);
        int p7 = atomicAdd(&g_cnt[m][rb.w], 1);

        if (p0 < CAP) g_slot[m][(size_t)ra.x * CAP + p0] = make_int2(ca.x, __float_as_int(va.x));
        if (p1 < CAP) g_slot[m][(size_t)ra.y * CAP + p1] = make_int2(ca.y, __float_as_int(va.y));
        if (p2 < CAP) g_slot[m][(size_t)ra.z * CAP + p2] = make_int2(ca.z, __float_as_int(va.z));
        if (p3 < CAP) g_slot[m][(size_t)ra.w * CAP + p3] = make_int2(ca.w, __float_as_int(va.w));
        if (p4 < CAP) g_slot[m][(size_t)rb.x * CAP + p4] = make_int2(cb.x, __float_as_int(vb.x));
        if (p5 < CAP) g_slot[m][(size_t)rb.y * CAP + p5] = make_int2(cb.y, __float_as_int(vb.y));
        if (p6 < CAP) g_slot[m][(size_t)rb.z * CAP + p6] = make_int2(cb.z, __float_as_int(vb.z));
        if (p7 < CAP) g_slot[m][(size_t)rb.w * CAP + p7] = make_int2(cb.w, __float_as_int(vb.w));
    } else {
        // ---- convert: one float4 -> two half2 ----
        int cbid = bid - (bid / 9 + 1);    // convert-block index
        int j = cbid * blockDim.x + threadIdx.x;
        if (j >= 2 * n4) return;
        int m = j < n4 ? 0 : 1;
        int k = m ? j - n4 : j;
        float4 v = __ldg(m ? &x2[k] : &x1[k]);
        __half2* dst = &g_xh[m][(size_t)k * 2];
        dst[0] = __floats2half2_rn(v.x, v.y);
        dst[1] = __floats2half2_rn(v.z, v.w);
    }
}

// Warp-per-2-rows gather SpMM — R15 loop, UNMASKED (zero-slot invariant).
__global__ void __launch_bounds__(256) spmm_kernel(
    float* __restrict__ out1,
    float* __restrict__ out2,
    int n_nodes)
{
    int tid  = blockIdx.x * blockDim.x + threadIdx.x;
    int warp = tid >> 5;
    int lane = threadIdx.x & 31;
    int half_id = lane >> 4;      // which of the warp's 2 rows
    int gl      = lane & 15;      // lane within the 16-lane group

    int g = warp * 2 + half_id;   // row slot across both matrices
    if (g >= 2 * n_nodes) return;

    int m = g < n_nodes ? 0 : 1;
    int r = m ? g - n_nodes : g;
    const uint2* x = (const uint2*)g_xh[m];
    float* out     = m ? out2 : out1;

    int n = g_cnt[m][r];
    if (n > CAP) n = CAP;

    const int4* ep = (const int4*)&g_slot[m][(size_t)r * CAP];  // 2 edges / int4

    float4 acc = make_float4(0.f, 0.f, 0.f, 0.f);
    int iters = (n + 3) >> 2;     // 4 edges / iteration; tail slots are
                                  // (col=0, val=0) by the zero-slot invariant

    if (iters > 0) {
        int4 e01 = __ldg(ep + 0);
        int4 e23 = __ldg(ep + 1);
        for (int it = 0; it < iters; it++) {
            int4 n01, n23;
            if (it + 1 < iters) {
                n01 = __ldg(ep + 2 * it + 2);
                n23 = __ldg(ep + 2 * it + 3);
            }
            float v0 = __int_as_float(e01.y);
            float v1 = __int_as_float(e01.w);
            float v2 = __int_as_float(e23.y);
            float v3 = __int_as_float(e23.w);

            uint2 ua = __ldg(&x[(size_t)e01.x * U2_PER_ROW + gl]);
            uint2 ub = __ldg(&x[(size_t)e01.z * U2_PER_ROW + gl]);
            uint2 uc = __ldg(&x[(size_t)e23.x * U2_PER_ROW + gl]);
            uint2 ud = __ldg(&x[(size_t)e23.z * U2_PER_ROW + gl]);

            float2 a0 = __half22float2(*(__half2*)&ua.x);
            float2 a1 = __half22float2(*(__half2*)&ua.y);
            float2 b0 = __half22float2(*(__half2*)&ub.x);
            float2 b1 = __half22float2(*(__half2*)&ub.y);
            float2 c0f = __half22float2(*(__half2*)&uc.x);
            float2 c1f = __half22float2(*(__half2*)&uc.y);
            float2 d0 = __half22float2(*(__half2*)&ud.x);
            float2 d1 = __half22float2(*(__half2*)&ud.y);

            acc.x += v0 * a0.x + v1 * b0.x + v2 * c0f.x + v3 * d0.x;
            acc.y += v0 * a0.y + v1 * b0.y + v2 * c0f.y + v3 * d0.y;
            acc.z += v0 * a1.x + v1 * b1.x + v2 * c1f.x + v3 * d1.x;
            acc.w += v0 * a1.y + v1 * b1.y + v2 * c1f.y + v3 * d1.y;

            e01 = n01;
            e23 = n23;
        }
    }

    // 16 lanes x float4 = 256B coalesced store per row.
    ((float4*)(out + (size_t)r * DFEAT))[gl] = acc;
}

// --------------------------------------------------------------- launch ----

extern "C" void kernel_launch(void* const* d_in, const int* in_sizes, int n_in,
                              void* d_out, int out_size) {
    const float* x1      = (const float*)d_in[0];
    const float* x2      = (const float*)d_in[1];
    const int*   a1_rows = (const int*)d_in[2];
    const int*   a1_cols = (const int*)d_in[3];
    const float* a1_vals = (const float*)d_in[4];
    const int*   a2_rows = (const int*)d_in[5];
    const int*   a2_cols = (const int*)d_in[6];
    const float* a2_vals = (const float*)d_in[7];

    float* out  = (float*)d_out;
    int n_edges = in_sizes[2];               // 1048576
    int n_nodes = in_sizes[0] / DFEAT;       // 65536
    int half    = n_nodes * DFEAT;

    // 1) zero per-row counters (must precede bucket atomics)
    {
        int ncnt4 = 2 * n_nodes / 4;         // 32768 int4 words
        zero_cnt_kernel<<<(ncnt4 + 255) / 256, 256>>>(ncnt4);
    }

    // 2) interleaved prep: bucket (1024 blocks) striped into convert (8192)
    {
        int nbucket = 2 * n_edges / 8;       // 262144 threads -> 1024 blocks
        int n4 = n_nodes * DFEAT / 4;        // 1M float4 per matrix -> 8192 blocks
        int nblocks = (nbucket / 256) + (2 * n4 / 256);   // 9216
        prep_kernel<<<nblocks, 256>>>(
            (const int4*)a1_rows, (const int4*)a1_cols, (const float4*)a1_vals,
            (const int4*)a2_rows, (const int4*)a2_cols, (const float4*)a2_vals,
            (const float4*)x1, (const float4*)x2,
            nbucket, n4);
    }

    // 3) warp-per-2-rows gather SpMM (unmasked, fp16 gathers, fp32 accumulate)
    {
        long long total_threads = 1LL * n_nodes * 32;   // 1 warp per 2 rows
        int threads = 256;
        long long blocks = (total_threads + threads - 1) / threads;
        spmm_kernel<<<(unsigned)blocks, threads>>>(out, out + half, n_nodes);
    }
}